// round 11
// baseline (speedup 1.0000x reference)
#include <cuda_runtime.h>

// Fused pre-norm attention-downsampling:
//   out[b,s,:] = q[b,s,:] + sum_f (LN(q[b,s]) . LN(k[b,4s+f])) * LN(v[b,4s+f])
// B=4, Sq=2048, Skv=8192, D=1024, factor=4.
// R10: R8 skeleton (deferred-v, 5 CTAs/SM) with a shallow-butterfly reduction:
//  - only 3 shuffle levels (offsets 16,8,4); the remaining 4 partials per value
//    are resolved in the smem combine. SHFL per CTA-row: 880 -> 528.
//  - vectorized STS (slot = lane index) replaces 22 scalar lane-0 stores.
//  - cross-warp combine reads partials as coalesced LDS.128.

#define DD 1024
#define NT 256
#define NW 8
#define FACTOR 4
#define LN_EPS 1e-5f
#define WSTRIDE 48            // 12 values * 4 partials per warp
#define SMB (NW * WSTRIDE)    // 384 floats of partials; bcast after

// Batched block reduction of N values (8 < N <= 12), 2 barriers.
// 3-level butterfly: lane l ends holding partial class (l&3) of every value.
template <int N>
__device__ __forceinline__ void block_reduce(float (&val)[N], float* sm) {
#pragma unroll
    for (int i = 0; i < N; i++) {
        val[i] += __shfl_xor_sync(0xffffffffu, val[i], 16);
        val[i] += __shfl_xor_sync(0xffffffffu, val[i], 8);
        val[i] += __shfl_xor_sync(0xffffffffu, val[i], 4);
    }
    const int w = threadIdx.x >> 5;
    const int l = threadIdx.x & 31;

    // slot = value*4 + partial; with value = l>>2, partial = l&3 -> slot = l.
    float mine = val[0];
#pragma unroll
    for (int i = 1; i < 8; i++) mine = ((l >> 2) == i) ? val[i] : mine;
    sm[w * WSTRIDE + l] = mine;
    // pass 2: values 8..N-1 -> slots 32 + l
    float mine2 = val[8];
#pragma unroll
    for (int i = 9; i < N; i++) mine2 = ((l >> 2) + 8 == i) ? val[i] : mine2;
    if (l < 4 * (N - 8)) sm[w * WSTRIDE + 32 + l] = mine2;
    __syncthreads();

    if (threadIdx.x < N) {
        float tot = 0.f;
#pragma unroll
        for (int j = 0; j < NW; j++) {
            const float4 p =
                *(const float4*)&sm[j * WSTRIDE + threadIdx.x * 4];
            tot += (p.x + p.y) + (p.z + p.w);
        }
        sm[SMB + threadIdx.x] = tot;
    }
    __syncthreads();
#pragma unroll
    for (int i = 0; i < N; i++) val[i] = sm[SMB + i];
}

__device__ __forceinline__ float hsum(const float4 a) {
    return (a.x + a.y) + (a.z + a.w);
}
__device__ __forceinline__ float hsq(const float4 a) {
    return (a.x * a.x + a.y * a.y) + (a.z * a.z + a.w * a.w);
}

__global__ __launch_bounds__(NT, 5) void attn_ds_kernel(
    const float* __restrict__ q, const float* __restrict__ k,
    const float* __restrict__ v, const float* __restrict__ lnw,
    const float* __restrict__ lnb, float* __restrict__ out) {
    __shared__ __align__(16) float sm[SMB + 12];

    const int bid = blockIdx.x;          // b*2048 + s
    const int b = bid >> 11;
    const int s = bid & 2047;
    const int t = threadIdx.x;
    const float invD = 1.0f / (float)DD;

    const float4* q4 = (const float4*)q + (size_t)bid * (DD / 4);
    const size_t kvo = ((size_t)b * 8192 + (size_t)s * FACTOR) * (DD / 4);
    const float4* k4 = (const float4*)k + kvo;
    const float4* v4 = (const float4*)v + kvo;

    // Front-batched loads for phase 1: q + 4k + w/b (7 LDG.128).
    const float4 qv = q4[t];
    const float4 wv = ((const float4*)lnw)[t];
    const float4 bv = ((const float4*)lnb)[t];
    float4 kr[FACTOR];
#pragma unroll
    for (int f = 0; f < FACTOR; f++) kr[f] = k4[f * (DD / 4) + t];

    // ---- Phase 1: q + k stats (10 values, one reduction) ----
    float r1[10];
    r1[0] = hsum(qv);
    r1[1] = hsq(qv);
#pragma unroll
    for (int f = 0; f < FACTOR; f++) {
        r1[2 + 2 * f] = hsum(kr[f]);
        r1[3 + 2 * f] = hsq(kr[f]);
    }
    block_reduce<10>(r1, sm);

    const float mu = r1[0] * invD;
    const float rs = rsqrtf(fmaf(-mu, mu, r1[1] * invD) + LN_EPS);
    float4 qn;
    qn.x = fmaf((qv.x - mu) * rs, wv.x, bv.x);
    qn.y = fmaf((qv.y - mu) * rs, wv.y, bv.y);
    qn.z = fmaf((qv.z - mu) * rs, wv.z, bv.z);
    qn.w = fmaf((qv.w - mu) * rs, wv.w, bv.w);

    // ---- Phase 2: dot partials; v_f loaded as k_f dies ----
    float4 vr[FACTOR];
    float r2[12];
#pragma unroll
    for (int f = 0; f < FACTOR; f++) {
        const float muk = r1[2 + 2 * f] * invD;
        const float rsk =
            rsqrtf(fmaf(-muk, muk, r1[3 + 2 * f] * invD) + LN_EPS);
        const float4 kv = kr[f];
        const float knx = fmaf((kv.x - muk) * rsk, wv.x, bv.x);
        const float kny = fmaf((kv.y - muk) * rsk, wv.y, bv.y);
        const float knz = fmaf((kv.z - muk) * rsk, wv.z, bv.z);
        const float knw = fmaf((kv.w - muk) * rsk, wv.w, bv.w);
        r2[f] = (knx * qn.x + kny * qn.y) + (knz * qn.z + knw * qn.w);
        vr[f] = v4[f * (DD / 4) + t];   // k_f register slots freed -> v_f
    }
#pragma unroll
    for (int f = 0; f < FACTOR; f++) {
        r2[4 + f] = hsum(vr[f]);
        r2[8 + f] = hsq(vr[f]);
    }
    block_reduce<12>(r2, sm);

    // ---- Epilogue: residual + weighted LN(v) ----
    float4 acc = qv;
#pragma unroll
    for (int f = 0; f < FACTOR; f++) {
        const float wt = r2[f];
        const float muv = r2[4 + f] * invD;
        const float rsv =
            rsqrtf(fmaf(-muv, muv, r2[8 + f] * invD) + LN_EPS);
        const float4 vv = vr[f];
        acc.x = fmaf(wt, fmaf((vv.x - muv) * rsv, wv.x, bv.x), acc.x);
        acc.y = fmaf(wt, fmaf((vv.y - muv) * rsv, wv.y, bv.y), acc.y);
        acc.z = fmaf(wt, fmaf((vv.z - muv) * rsv, wv.z, bv.z), acc.z);
        acc.w = fmaf(wt, fmaf((vv.w - muv) * rsv, wv.w, bv.w), acc.w);
    }

    ((float4*)out + (size_t)bid * (DD / 4))[t] = acc;
}

extern "C" void kernel_launch(void* const* d_in, const int* in_sizes, int n_in,
                              void* d_out, int out_size) {
    const float* q   = (const float*)d_in[0];  // query     [4,2048,1024]
    const float* k   = (const float*)d_in[1];  // key       [4,8192,1024]
    const float* v   = (const float*)d_in[2];  // value     [4,8192,1024]
    const float* lnw = (const float*)d_in[3];  // ln_weight [1024]
    const float* lnb = (const float*)d_in[4];  // ln_bias   [1024]
    float* out = (float*)d_out;                // [4,2048,1024]

    attn_ds_kernel<<<4 * 2048, NT>>>(q, k, v, lnw, lnb, out);
}

// round 12
// speedup vs baseline: 1.4452x; 1.4452x over previous
#include <cuda_runtime.h>

// Fused pre-norm attention-downsampling:
//   out[b,s,:] = q[b,s,:] + sum_f (LN(q[b,s]) . LN(k[b,4s+f])) * LN(v[b,4s+f])
// B=4, Sq=2048, Skv=8192, D=1024, factor=4.
// R11: R8 skeleton + 3-level butterfly with DIRECT partial stores (no SELs).
//  - 3 shuffle levels (16,8,4): lane l holds partial class (l&3) of every
//    value. Lanes 0-3 store all N values straight from the register array
//    (constant-offset STS, 1 wavefront each). SHFL per CTA-row: 880 -> 528.
//  - combine reads partials as LDS.128; broadcast back as float4 loads.

#define DD 1024
#define NT 256
#define NW 8
#define FACTOR 4
#define LN_EPS 1e-5f
#define WSTRIDE 48            // 12 values * 4 partials per warp (floats)
#define SMB (NW * WSTRIDE)    // 384 floats of partials; bcast region after

// Batched block reduction of N values (N <= 12), 2 barriers, no SEL chains.
template <int N>
__device__ __forceinline__ void block_reduce(float (&val)[N], float* sm) {
#pragma unroll
    for (int i = 0; i < N; i++) {
        val[i] += __shfl_xor_sync(0xffffffffu, val[i], 16);
        val[i] += __shfl_xor_sync(0xffffffffu, val[i], 8);
        val[i] += __shfl_xor_sync(0xffffffffu, val[i], 4);
    }
    const int w = threadIdx.x >> 5;
    const int l = threadIdx.x & 31;

    // Lanes 0-3 each store their partial of ALL values (direct indexing).
    if (l < 4) {
#pragma unroll
        for (int i = 0; i < N; i++) sm[w * WSTRIDE + i * 4 + l] = val[i];
    }
    __syncthreads();

    // Thread i (< N) folds 8 warps x 4 partials via LDS.128.
    if (threadIdx.x < N) {
        float tot = 0.f;
#pragma unroll
        for (int j = 0; j < NW; j++) {
            const float4 p =
                *(const float4*)&sm[j * WSTRIDE + threadIdx.x * 4];
            tot += (p.x + p.y) + (p.z + p.w);
        }
        sm[SMB + threadIdx.x] = tot;
    }
    __syncthreads();

    // Vectorized broadcast read-back.
#pragma unroll
    for (int i = 0; i < N; i += 4) {
        const float4 bb = *(const float4*)&sm[SMB + i];
        val[i] = bb.x;
        if (i + 1 < N) val[i + 1] = bb.y;
        if (i + 2 < N) val[i + 2] = bb.z;
        if (i + 3 < N) val[i + 3] = bb.w;
    }
}

__device__ __forceinline__ float hsum(const float4 a) {
    return (a.x + a.y) + (a.z + a.w);
}
__device__ __forceinline__ float hsq(const float4 a) {
    return (a.x * a.x + a.y * a.y) + (a.z * a.z + a.w * a.w);
}

__global__ __launch_bounds__(NT, 5) void attn_ds_kernel(
    const float* __restrict__ q, const float* __restrict__ k,
    const float* __restrict__ v, const float* __restrict__ lnw,
    const float* __restrict__ lnb, float* __restrict__ out) {
    __shared__ __align__(16) float sm[SMB + 12];

    const int bid = blockIdx.x;          // b*2048 + s
    const int b = bid >> 11;
    const int s = bid & 2047;
    const int t = threadIdx.x;
    const float invD = 1.0f / (float)DD;

    const float4* q4 = (const float4*)q + (size_t)bid * (DD / 4);
    const size_t kvo = ((size_t)b * 8192 + (size_t)s * FACTOR) * (DD / 4);
    const float4* k4 = (const float4*)k + kvo;
    const float4* v4 = (const float4*)v + kvo;

    // Front-batched loads for phase 1: q + 4k + w/b (7 LDG.128).
    const float4 qv = q4[t];
    const float4 wv = ((const float4*)lnw)[t];
    const float4 bv = ((const float4*)lnb)[t];
    float4 kr[FACTOR];
#pragma unroll
    for (int f = 0; f < FACTOR; f++) kr[f] = k4[f * (DD / 4) + t];

    // ---- Phase 1: q + k stats (10 values, one reduction) ----
    float r1[10];
    r1[0] = hsum(qv);
    r1[1] = hsq(qv);
#pragma unroll
    for (int f = 0; f < FACTOR; f++) {
        r1[2 + 2 * f] = hsum(kr[f]);
        r1[3 + 2 * f] = hsq(kr[f]);
    }
    block_reduce<10>(r1, sm);

    const float mu = r1[0] * invD;
    const float rs = rsqrtf(fmaf(-mu, mu, r1[1] * invD) + LN_EPS);
    float4 qn;
    qn.x = fmaf((qv.x - mu) * rs, wv.x, bv.x);
    qn.y = fmaf((qv.y - mu) * rs, wv.y, bv.y);
    qn.z = fmaf((qv.z - mu) * rs, wv.z, bv.z);
    qn.w = fmaf((qv.w - mu) * rs, wv.w, bv.w);

    // ---- Phase 2: dot partials; v_f loaded as k_f dies ----
    float4 vr[FACTOR];
    float r2[12];
#pragma unroll
    for (int f = 0; f < FACTOR; f++) {
        const float muk = r1[2 + 2 * f] * invD;
        const float rsk =
            rsqrtf(fmaf(-muk, muk, r1[3 + 2 * f] * invD) + LN_EPS);
        const float4 kv = kr[f];
        const float knx = fmaf((kv.x - muk) * rsk, wv.x, bv.x);
        const float kny = fmaf((kv.y - muk) * rsk, wv.y, bv.y);
        const float knz = fmaf((kv.z - muk) * rsk, wv.z, bv.z);
        const float knw = fmaf((kv.w - muk) * rsk, wv.w, bv.w);
        r2[f] = (knx * qn.x + kny * qn.y) + (knz * qn.z + knw * qn.w);
        vr[f] = v4[f * (DD / 4) + t];   // k_f register slots freed -> v_f
    }
#pragma unroll
    for (int f = 0; f < FACTOR; f++) {
        r2[4 + f] = hsum(vr[f]);
        r2[8 + f] = hsq(vr[f]);
    }
    block_reduce<12>(r2, sm);

    // ---- Epilogue: residual + weighted LN(v) ----
    float4 acc = qv;
#pragma unroll
    for (int f = 0; f < FACTOR; f++) {
        const float wt = r2[f];
        const float muv = r2[4 + f] * invD;
        const float rsv =
            rsqrtf(fmaf(-muv, muv, r2[8 + f] * invD) + LN_EPS);
        const float4 vv = vr[f];
        acc.x = fmaf(wt, fmaf((vv.x - muv) * rsv, wv.x, bv.x), acc.x);
        acc.y = fmaf(wt, fmaf((vv.y - muv) * rsv, wv.y, bv.y), acc.y);
        acc.z = fmaf(wt, fmaf((vv.z - muv) * rsv, wv.z, bv.z), acc.z);
        acc.w = fmaf(wt, fmaf((vv.w - muv) * rsv, wv.w, bv.w), acc.w);
    }

    ((float4*)out + (size_t)bid * (DD / 4))[t] = acc;
}

extern "C" void kernel_launch(void* const* d_in, const int* in_sizes, int n_in,
                              void* d_out, int out_size) {
    const float* q   = (const float*)d_in[0];  // query     [4,2048,1024]
    const float* k   = (const float*)d_in[1];  // key       [4,8192,1024]
    const float* v   = (const float*)d_in[2];  // value     [4,8192,1024]
    const float* lnw = (const float*)d_in[3];  // ln_weight [1024]
    const float* lnb = (const float*)d_in[4];  // ln_bias   [1024]
    float* out = (float*)d_out;                // [4,2048,1024]

    attn_ds_kernel<<<4 * 2048, NT>>>(q, k, v, lnw, lnb, out);
}